// round 3
// baseline (speedup 1.0000x reference)
#include <cuda_runtime.h>
#include <cstdint>

// Problem constants (fixed by reference setup_inputs).
constexpr int N_MOLS      = 2000;
constexpr int N_PER_MOL   = 64;
constexpr int PAIRS_PER_M = N_PER_MOL * (N_PER_MOL - 1);   // 4032
constexpr int CHUNKS      = PAIRS_PER_M / 4;               // 1008 chunks of 4 pairs
constexpr float CUTOFF    = 5.0f;

// Output layout (flatten of reference tuple, all float32):
//   [0,    P)  : i_idx
//   [P,   2P)  : j_idx
//   [2P,  3P)  : d_ij
//   [3P,  6P)  : r_ij (row-major [P,3])
// with P = N_MOLS * PAIRS_PER_M = 8,064,000.

__device__ __forceinline__ void stcs4(float* p, float4 v) {
    __stcs((float4*)p, v);
}

__global__ __launch_bounds__(256)
void neighborlist_kernel(const float* __restrict__ pos, float* __restrict__ out)
{
    __shared__ float sx[N_PER_MOL];
    __shared__ float sy[N_PER_MOL];
    __shared__ float sz[N_PER_MOL];

    const int m = blockIdx.x;
    const int t = threadIdx.x;

    if (t < N_PER_MOL) {
        const float* p = pos + (size_t)(m * N_PER_MOL + t) * 3;
        sx[t] = p[0];
        sy[t] = p[1];
        sz[t] = p[2];
    }
    __syncthreads();

    const size_t P = (size_t)N_MOLS * PAIRS_PER_M;
    float* __restrict__ out_i = out;
    float* __restrict__ out_j = out + P;
    float* __restrict__ out_d = out + 2 * P;
    float* __restrict__ out_r = out + 3 * P;

    const size_t base    = (size_t)m * PAIRS_PER_M;
    const float  fabase  = (float)(m * N_PER_MOL);

    for (int c = t; c < CHUNKS; c += 256) {
        const int p0 = c * 4;
        int i  = p0 / 63;            // one const-div per 4 pairs
        int jr = p0 - i * 63;

        float fi[4], fj[4], fd[4], fr[12];

        #pragma unroll
        for (int k = 0; k < 4; k++) {
            const int j = jr + (jr >= i ? 1 : 0);

            const float dx = sx[j] - sx[i];
            const float dy = sy[j] - sy[i];
            const float dz = sz[j] - sz[i];
            const float d  = sqrtf(fmaf(dx, dx, fmaf(dy, dy, dz * dz)));

            const bool in_cut = (d <= CUTOFF);
            fi[k] = fabase + (float)i;
            fj[k] = fabase + (float)j;
            fd[k] = in_cut ? d  : 0.0f;
            fr[3*k + 0] = in_cut ? dx : 0.0f;
            fr[3*k + 1] = in_cut ? dy : 0.0f;
            fr[3*k + 2] = in_cut ? dz : 0.0f;

            // advance (i, jr) to next ordered pair
            jr += 1;
            const int wrap = (jr == 63);
            i  += wrap;
            jr  = wrap ? 0 : jr;
        }

        const size_t g = base + p0;             // multiple of 4 -> 16B aligned
        stcs4(out_i + g, make_float4(fi[0], fi[1], fi[2], fi[3]));
        stcs4(out_j + g, make_float4(fj[0], fj[1], fj[2], fj[3]));
        stcs4(out_d + g, make_float4(fd[0], fd[1], fd[2], fd[3]));

        float* r = out_r + 3 * g;               // 3g multiple of 12 -> 16B aligned
        stcs4(r + 0, make_float4(fr[0], fr[1], fr[2],  fr[3]));
        stcs4(r + 4, make_float4(fr[4], fr[5], fr[6],  fr[7]));
        stcs4(r + 8, make_float4(fr[8], fr[9], fr[10], fr[11]));
    }
}

extern "C" void kernel_launch(void* const* d_in, const int* in_sizes, int n_in,
                              void* d_out, int out_size)
{
    const float* pos = (const float*)d_in[0];
    float* out = (float*)d_out;
    neighborlist_kernel<<<N_MOLS, 256>>>(pos, out);
}